// round 16
// baseline (speedup 1.0000x reference)
#include <cuda_runtime.h>
#include <cuda_fp16.h>
#include <math.h>
#include <stdint.h>

#define HS   768
#define NH   12
#define HD   64
#define FF   3072
#define BB   4
#define SS   2048
#define MM   (BB*SS)     /* 8192 rows */
#define H3   (3*HS)      /* 2304 */

// ---------------- scratch (device globals, no allocation) ----------------
__device__ __half g_xh   [(size_t)MM * HS];
__device__ __half g_wqkvT[(size_t)H3 * HS];
__device__ __half g_woutT[(size_t)HS * HS];
__device__ __half g_wff1T[(size_t)FF * HS];
__device__ __half g_wff2T[(size_t)HS * FF];
__device__ __half g_qkvh [(size_t)MM * H3];
__device__ __half g_ctxh [(size_t)MM * HS];
__device__ __half g_aoh  [(size_t)MM * HS];
__device__ __half g_x1h  [(size_t)MM * HS];
__device__ __half g_h1h  [(size_t)MM * FF];
__device__ __half g_f2p  [(size_t)2 * MM * HS];   /* split-K partials */

// ================= helpers ==================================================
__device__ __forceinline__ uint32_t smem_u32(const void* p) {
    uint32_t a;
    asm("{ .reg .u64 t; cvta.to.shared.u64 t, %1; cvt.u32.u64 %0, t; }" : "=r"(a) : "l"(p));
    return a;
}
__device__ __forceinline__ void cp16(uint32_t s, const void* g) {
    asm volatile("cp.async.cg.shared.global [%0], [%1], 16;" :: "r"(s), "l"(g) : "memory");
}
__device__ __forceinline__ void cp_commit() {
    asm volatile("cp.async.commit_group;" ::: "memory");
}
template<int N> __device__ __forceinline__ void cp_wait() {
    asm volatile("cp.async.wait_group %0;" :: "n"(N) : "memory");
}
__device__ __forceinline__ void mma_f16(float c[4], const uint32_t a[4], const uint32_t b[2]) {
    asm volatile(
        "mma.sync.aligned.m16n8k16.row.col.f32.f16.f16.f32 "
        "{%0,%1,%2,%3}, {%4,%5,%6,%7}, {%8,%9}, {%0,%1,%2,%3};"
        : "+f"(c[0]), "+f"(c[1]), "+f"(c[2]), "+f"(c[3])
        : "r"(a[0]), "r"(a[1]), "r"(a[2]), "r"(a[3]), "r"(b[0]), "r"(b[1]));
}
__device__ __forceinline__ void ldmx4(uint32_t r[4], uint32_t addr) {
    asm volatile("ldmatrix.sync.aligned.m8n8.x4.shared.b16 {%0,%1,%2,%3}, [%4];"
                 : "=r"(r[0]), "=r"(r[1]), "=r"(r[2]), "=r"(r[3]) : "r"(addr));
}
__device__ __forceinline__ void ldmx2t(uint32_t& b0, uint32_t& b1, uint32_t addr) {
    asm volatile("ldmatrix.sync.aligned.m8n8.x2.trans.shared.b16 {%0,%1}, [%2];"
                 : "=r"(b0), "=r"(b1) : "r"(addr));
}
__device__ __forceinline__ float gelu_exact(float v) {
    return 0.5f * v * (1.0f + erff(v * 0.70710678118654752f));
}

// ---------------- fused pre-pass: f2h(x) + 4 weight transposes -------------
__device__ __forceinline__ void transp_tile(const float* __restrict__ W,
                                            __half* __restrict__ WT,
                                            int K, int N, int bx, int by,
                                            int tx, int ty, float* t /*32x33*/)
{
    const int n0 = bx * 32, k0 = by * 32;
#pragma unroll
    for (int i = 0; i < 4; i++)
        t[(ty + i * 8) * 33 + tx] = W[(size_t)(k0 + ty + i * 8) * N + n0 + tx];
    __syncthreads();
#pragma unroll
    for (int i = 0; i < 4; i++)
        WT[(size_t)(n0 + ty + i * 8) * K + k0 + tx] = __float2half_rn(t[tx * 33 + ty + i * 8]);
}

#define PREP_F2H   6144
#define PREP_QKV   (72 * 24)
#define PREP_OUT   (24 * 24)
#define PREP_FF1   (96 * 24)
#define PREP_FF2   (24 * 96)
#define PREP_TOTAL (PREP_F2H + PREP_QKV + PREP_OUT + PREP_FF1 + PREP_FF2)

__global__ void __launch_bounds__(256)
prep_kernel(const float* __restrict__ x,
            const float* __restrict__ wqkv, const float* __restrict__ wout,
            const float* __restrict__ wff1, const float* __restrict__ wff2,
            __half* __restrict__ xh,
            __half* __restrict__ wqkvT, __half* __restrict__ woutT,
            __half* __restrict__ wff1T, __half* __restrict__ wff2T)
{
    __shared__ float t[32 * 33];
    int blk = blockIdx.x;
    const int tid = threadIdx.x;
    if (blk < PREP_F2H) {
        int i = blk * 256 + tid;
        float4 v = *(const float4*)(x + (size_t)i * 4);
        __half2 h0 = __floats2half2_rn(v.x, v.y);
        __half2 h1 = __floats2half2_rn(v.z, v.w);
        *(uint2*)(xh + (size_t)i * 4) = make_uint2(*(uint32_t*)&h0, *(uint32_t*)&h1);
        return;
    }
    blk -= PREP_F2H;
    const int tx = tid & 31, ty = tid >> 5;
    if (blk < PREP_QKV) {
        transp_tile(wqkv, wqkvT, HS, H3, blk % 72, blk / 72, tx, ty, t);
        return;
    }
    blk -= PREP_QKV;
    if (blk < PREP_OUT) {
        transp_tile(wout, woutT, HS, HS, blk % 24, blk / 24, tx, ty, t);
        return;
    }
    blk -= PREP_OUT;
    if (blk < PREP_FF1) {
        transp_tile(wff1, wff1T, HS, FF, blk % 96, blk / 96, tx, ty, t);
        return;
    }
    blk -= PREP_FF1;
    transp_tile(wff2, wff2T, FF, HS, blk % 24, blk / 24, tx, ty, t);
}

// ---------------- fp16 mma GEMM: BK=64, 3-stage cp.async -------------------
// SPLITK: blockIdx.z selects K-half; no bias/GELU; writes partial buffer z.
#define PITCH  72
#define AST    (128 * PITCH)
#define STG_H  (2 * AST)
#define STAGES 3
#define GH_SMEM_BYTES (STAGES * STG_H * 2)

template<int GELU, int SPLITK>
__global__ void __launch_bounds__(256, 2)
gemm_h(const __half* __restrict__ A, const __half* __restrict__ WT,
       const float* __restrict__ bias, __half* __restrict__ Ch,
       int N, int K)
{
    extern __shared__ __half hsm[];
    const uint32_t sbase = smem_u32(hsm);

    const int tid  = threadIdx.x;
    const int warp = tid >> 5;
    const int lane = tid & 31;
    const int g    = lane >> 2;
    const int t    = lane & 3;
    const int wm   = warp >> 2;
    const int wn   = warp & 3;
    const int row0 = blockIdx.y * 128;
    const int col0 = blockIdx.x * 128;

    int KL = K;                 // local K span for this block
    int kbase = 0;
    if (SPLITK) {
        KL = K >> 1;
        kbase = blockIdx.z * KL;
        Ch += (size_t)blockIdx.z * MM * HS;
    }
    const int KT = KL >> 6;

    const __half* Ab = A  + (size_t)row0 * K + kbase;
    const __half* Bb = WT + (size_t)col0 * K + kbase;

    const int lm_arow = wm * 64 + (lane & 15);
    const int lm_acol = (lane >> 4) * 8;
    const int lm_brow = wn * 32 + (lane & 7) + ((lane >> 4) << 3);
    const int lm_bcol = ((lane >> 3) & 1) * 8;

    float acc[4][4][4];
#pragma unroll
    for (int mi = 0; mi < 4; mi++)
#pragma unroll
        for (int ni = 0; ni < 4; ni++)
#pragma unroll
            for (int q = 0; q < 4; q++) acc[mi][ni][q] = 0.f;

#pragma unroll
    for (int s = 0; s < 2; s++) {
        const uint32_t sa = sbase + s * STG_H * 2;
        const int k0 = s * 64;
#pragma unroll
        for (int j = 0; j < 4; j++) {
            int item = tid + j * 256;
            int r = item >> 3, c = item & 7;
            cp16(sa + (r * PITCH + c * 8) * 2,       Ab + (size_t)r * K + k0 + c * 8);
            cp16(sa + (AST + r * PITCH + c * 8) * 2, Bb + (size_t)r * K + k0 + c * 8);
        }
        cp_commit();
    }

    int stg = 0;
    for (int it = 0; it < KT; it++) {
        if (it + 1 < KT) cp_wait<1>();
        else             cp_wait<0>();
        __syncthreads();

        if (it + 2 < KT) {
            int s = stg + 2; if (s >= STAGES) s -= STAGES;
            const uint32_t sa = sbase + s * STG_H * 2;
            const int k0 = (it + 2) * 64;
#pragma unroll
            for (int j = 0; j < 4; j++) {
                int item = tid + j * 256;
                int r = item >> 3, c = item & 7;
                cp16(sa + (r * PITCH + c * 8) * 2,       Ab + (size_t)r * K + k0 + c * 8);
                cp16(sa + (AST + r * PITCH + c * 8) * 2, Bb + (size_t)r * K + k0 + c * 8);
            }
            cp_commit();
        }

        const uint32_t cAu = sbase + (uint32_t)(stg * STG_H) * 2;
        const uint32_t cBu = cAu + AST * 2;
#pragma unroll
        for (int ks = 0; ks < 4; ks++) {
            const int kb = ks * 16;
            uint32_t af[4][4], bf[4][2];
#pragma unroll
            for (int mi = 0; mi < 4; mi++)
                ldmx4(af[mi], cAu + (((lm_arow + mi * 16) * PITCH) + kb + lm_acol) * 2);
#pragma unroll
            for (int nip = 0; nip < 2; nip++) {
                uint32_t r[4];
                ldmx4(r, cBu + (((lm_brow + nip * 16) * PITCH) + kb + lm_bcol) * 2);
                bf[nip * 2][0]     = r[0];
                bf[nip * 2][1]     = r[1];
                bf[nip * 2 + 1][0] = r[2];
                bf[nip * 2 + 1][1] = r[3];
            }
#pragma unroll
            for (int mi = 0; mi < 4; mi++)
#pragma unroll
                for (int ni = 0; ni < 4; ni++)
                    mma_f16(acc[mi][ni], af[mi], bf[ni]);
        }
        if (++stg == STAGES) stg = 0;
    }

#pragma unroll
    for (int mi = 0; mi < 4; mi++) {
        const int r0 = row0 + wm * 64 + mi * 16 + g;
#pragma unroll
        for (int ni = 0; ni < 4; ni++) {
            const int c = col0 + wn * 32 + ni * 8 + 2 * t;
            float v0 = acc[mi][ni][0];
            float v1 = acc[mi][ni][1];
            float v2 = acc[mi][ni][2];
            float v3 = acc[mi][ni][3];
            if (!SPLITK) {
                const float b0 = __ldg(bias + c);
                const float b1 = __ldg(bias + c + 1);
                v0 += b0; v1 += b1; v2 += b0; v3 += b1;
            }
            if (GELU) {
                v0 = gelu_exact(v0); v1 = gelu_exact(v1);
                v2 = gelu_exact(v2); v3 = gelu_exact(v3);
            }
            *(__half2*)(Ch + (size_t)r0 * N + c)       = __floats2half2_rn(v0, v1);
            *(__half2*)(Ch + (size_t)(r0 + 8) * N + c) = __floats2half2_rn(v2, v3);
        }
    }
}

// ---------------- fp16 flash attention (2-buffer, 2 CTAs/SM) ---------------
#define HP 72
#define AQ_OFF 0
#define AK_OFF (128 * HP)
#define AV_OFF (128 * HP + 2 * 64 * HP)
#define ATTN_SMEM_BYTES ((128 * HP + 4 * 64 * HP) * 2)

__global__ void __launch_bounds__(256, 2)
attn_mma(const __half* __restrict__ qkvh, __half* __restrict__ ctxh)
{
    extern __shared__ __half hsm[];
    __half* sQ = hsm + AQ_OFF;
    const uint32_t sb = smem_u32(hsm);

    const int tid  = threadIdx.x;
    const int warp = tid >> 5;
    const int lane = tid & 31;
    const int g    = lane >> 2;
    const int t    = lane & 3;
    const int m0   = warp * 16;
    const int l16  = lane & 15;

    const int q0 = blockIdx.x * 128;
    const int h  = blockIdx.y;
    const int b  = blockIdx.z;

    const __half* Qg = qkvh + ((size_t)(b * SS) + q0) * H3 + h * HD;
    const __half* Kg = qkvh + (size_t)(b * SS) * H3 + HS     + h * HD;
    const __half* Vg = qkvh + (size_t)(b * SS) * H3 + 2 * HS + h * HD;

    const int lm_krow = (lane & 7) + ((lane >> 4) << 3);
    const int lm_kcol = ((lane >> 3) & 1) * 8;

#pragma unroll
    for (int it = 0; it < 4; it++) {
        int item = tid + it * 256;
        int r = item >> 3, c = item & 7;
        *(uint4*)(sQ + r * HP + c * 8) = *(const uint4*)(Qg + (size_t)r * H3 + c * 8);
    }

    {
        const uint32_t ka = sb + AK_OFF * 2;
        const uint32_t va = sb + AV_OFF * 2;
#pragma unroll
        for (int it = 0; it < 2; it++) {
            int item = tid + it * 256;
            int j = item >> 3, c = item & 7;
            const size_t go = (size_t)j * H3 + c * 8;
            cp16(ka + (j * HP + c * 8) * 2, Kg + go);
            cp16(va + (j * HP + c * 8) * 2, Vg + go);
        }
        cp_commit();
    }
    __syncthreads();

    uint32_t qf[4][4];
#pragma unroll
    for (int kb = 0; kb < 4; kb++) {
        qf[kb][0] = *(const uint32_t*)(sQ + (m0 + g)     * HP + kb * 16 + 2 * t);
        qf[kb][1] = *(const uint32_t*)(sQ + (m0 + g + 8) * HP + kb * 16 + 2 * t);
        qf[kb][2] = *(const uint32_t*)(sQ + (m0 + g)     * HP + kb * 16 + 8 + 2 * t);
        qf[kb][3] = *(const uint32_t*)(sQ + (m0 + g + 8) * HP + kb * 16 + 8 + 2 * t);
    }

    float mrow0 = -1e30f, mrow1 = -1e30f;
    float lrow0 = 0.f,    lrow1 = 0.f;
    float o[8][4];
#pragma unroll
    for (int ni = 0; ni < 8; ni++)
#pragma unroll
        for (int q = 0; q < 4; q++) o[ni][q] = 0.f;

    const float scale = 0.125f;
    const int NT = SS / 64;

    for (int kt = 0; kt < NT; kt++) {
        cp_wait<0>();
        __syncthreads();

        const int buf = kt & 1;
        const uint32_t skb = sb + (AK_OFF + buf * 64 * HP) * 2;
        const uint32_t svb = sb + (AV_OFF + buf * 64 * HP) * 2;

        if (kt + 1 < NT) {
            const int nb = buf ^ 1;
            const uint32_t ka = sb + (AK_OFF + nb * 64 * HP) * 2;
            const uint32_t va = sb + (AV_OFF + nb * 64 * HP) * 2;
#pragma unroll
            for (int it = 0; it < 2; it++) {
                int item = tid + it * 256;
                int j = item >> 3, c = item & 7;
                const size_t go = (size_t)((kt + 1) * 64 + j) * H3 + c * 8;
                cp16(ka + (j * HP + c * 8) * 2, Kg + go);
                cp16(va + (j * HP + c * 8) * 2, Vg + go);
            }
            cp_commit();
        }

        float s_[8][4];
#pragma unroll
        for (int ni = 0; ni < 8; ni++)
#pragma unroll
            for (int q = 0; q < 4; q++) s_[ni][q] = 0.f;

#pragma unroll
        for (int kb = 0; kb < 4; kb++) {
#pragma unroll
            for (int nip = 0; nip < 4; nip++) {
                uint32_t r[4];
                ldmx4(r, skb + (((nip * 16 + lm_krow) * HP) + kb * 16 + lm_kcol) * 2);
                uint32_t bf0[2] = { r[0], r[1] };
                uint32_t bf1[2] = { r[2], r[3] };
                mma_f16(s_[nip * 2],     qf[kb], bf0);
                mma_f16(s_[nip * 2 + 1], qf[kb], bf1);
            }
        }

        float mn0 = -1e30f, mn1 = -1e30f;
#pragma unroll
        for (int ni = 0; ni < 8; ni++) {
            s_[ni][0] *= scale; s_[ni][1] *= scale;
            s_[ni][2] *= scale; s_[ni][3] *= scale;
            mn0 = fmaxf(mn0, fmaxf(s_[ni][0], s_[ni][1]));
            mn1 = fmaxf(mn1, fmaxf(s_[ni][2], s_[ni][3]));
        }
        mn0 = fmaxf(mn0, __shfl_xor_sync(0xffffffffu, mn0, 1));
        mn0 = fmaxf(mn0, __shfl_xor_sync(0xffffffffu, mn0, 2));
        mn1 = fmaxf(mn1, __shfl_xor_sync(0xffffffffu, mn1, 1));
        mn1 = fmaxf(mn1, __shfl_xor_sync(0xffffffffu, mn1, 2));

        const float mnew0 = fmaxf(mrow0, mn0);
        const float mnew1 = fmaxf(mrow1, mn1);
        const float a0 = __expf(mrow0 - mnew0);
        const float a1 = __expf(mrow1 - mnew1);
        mrow0 = mnew0; mrow1 = mnew1;

        float ladd0 = 0.f, ladd1 = 0.f;
#pragma unroll
        for (int ni = 0; ni < 8; ni++) {
            s_[ni][0] = __expf(s_[ni][0] - mnew0);
            s_[ni][1] = __expf(s_[ni][1] - mnew0);
            s_[ni][2] = __expf(s_[ni][2] - mnew1);
            s_[ni][3] = __expf(s_[ni][3] - mnew1);
            ladd0 += s_[ni][0] + s_[ni][1];
            ladd1 += s_[ni][2] + s_[ni][3];
            o[ni][0] *= a0; o[ni][1] *= a0;
            o[ni][2] *= a1; o[ni][3] *= a1;
        }
        ladd0 += __shfl_xor_sync(0xffffffffu, ladd0, 1);
        ladd0 += __shfl_xor_sync(0xffffffffu, ladd0, 2);
        ladd1 += __shfl_xor_sync(0xffffffffu, ladd1, 1);
        ladd1 += __shfl_xor_sync(0xffffffffu, ladd1, 2);
        lrow0 = lrow0 * a0 + ladd0;
        lrow1 = lrow1 * a1 + ladd1;

#pragma unroll
        for (int kb = 0; kb < 4; kb++) {
            uint32_t af[4];
            {
                __half2 h0 = __floats2half2_rn(s_[2 * kb][0],     s_[2 * kb][1]);
                __half2 h1 = __floats2half2_rn(s_[2 * kb][2],     s_[2 * kb][3]);
                __half2 h2 = __floats2half2_rn(s_[2 * kb + 1][0], s_[2 * kb + 1][1]);
                __half2 h3 = __floats2half2_rn(s_[2 * kb + 1][2], s_[2 * kb + 1][3]);
                af[0] = *(uint32_t*)&h0;
                af[1] = *(uint32_t*)&h1;
                af[2] = *(uint32_t*)&h2;
                af[3] = *(uint32_t*)&h3;
            }
            const uint32_t rowaddr = svb + ((kb * 16 + l16) * HP) * 2;
#pragma unroll
            for (int ni = 0; ni < 8; ni++) {
                uint32_t bf0, bf1;
                ldmx2t(bf0, bf1, rowaddr + ni * 16);
                uint32_t bf[2] = { bf0, bf1 };
                mma_f16(o[ni], af, bf);
            }
        }
    }

    const float inv0 = 1.0f / lrow0;
    const float inv1 = 1.0f / lrow1;
    const int qr0 = q0 + m0 + g;
    __half* dst0 = ctxh + ((size_t)(b * SS) + qr0)     * HS + h * HD;
    __half* dst1 = ctxh + ((size_t)(b * SS) + qr0 + 8) * HS + h * HD;
#pragma unroll
    for (int ni = 0; ni < 8; ni++) {
        const int c = ni * 8 + 2 * t;
        *(__half2*)(dst0 + c) = __floats2half2_rn(o[ni][0] * inv0, o[ni][1] * inv0);
        *(__half2*)(dst1 + c) = __floats2half2_rn(o[ni][2] * inv1, o[ni][3] * inv1);
    }
}

// ---------------- addln #1: x1h = LN(x_f32 + ao_h16) -----------------------
__global__ void __launch_bounds__(192)
addln_mid(const __half* __restrict__ a, const float* __restrict__ resf,
          const float* __restrict__ g, const float* __restrict__ bb,
          __half* __restrict__ outh)
{
    __shared__ float wsum[6], wsq[6];
    __shared__ float s_mu, s_rstd;

    const int row = blockIdx.x;
    const int tid = threadIdx.x;
    const int idx = tid * 4;

    uint2 ua = *(const uint2*)(a + (size_t)row * HS + idx);
    float4 vr = *(const float4*)(resf + (size_t)row * HS + idx);
    float2 a01 = __half22float2(*(__half2*)&ua.x);
    float2 a23 = __half22float2(*(__half2*)&ua.y);

    float v0 = a01.x + vr.x;
    float v1 = a01.y + vr.y;
    float v2 = a23.x + vr.z;
    float v3 = a23.y + vr.w;

    float sum = v0 + v1 + v2 + v3;
    float sq  = v0 * v0 + v1 * v1 + v2 * v2 + v3 * v3;
#pragma unroll
    for (int off = 16; off > 0; off >>= 1) {
        sum += __shfl_down_sync(0xffffffffu, sum, off);
        sq  += __shfl_down_sync(0xffffffffu, sq,  off);
    }
    if ((tid & 31) == 0) { wsum[tid >> 5] = sum; wsq[tid >> 5] = sq; }
    __syncthreads();
    if (tid == 0) {
        float s = 0.f, q = 0.f;
#pragma unroll
        for (int i = 0; i < 6; i++) { s += wsum[i]; q += wsq[i]; }
        float mu  = s * (1.f / HS);
        float var = q * (1.f / HS) - mu * mu;
        s_mu = mu;
        s_rstd = rsqrtf(fmaxf(var, 0.f) + 1e-12f);
    }
    __syncthreads();
    const float mu = s_mu, rstd = s_rstd;

    float4 vg = *(const float4*)(g  + idx);
    float4 vb = *(const float4*)(bb + idx);
    float r0 = (v0 - mu) * rstd * vg.x + vb.x;
    float r1 = (v1 - mu) * rstd * vg.y + vb.y;
    float r2 = (v2 - mu) * rstd * vg.z + vb.z;
    float r3 = (v3 - mu) * rstd * vg.w + vb.w;

    __half2 h0 = __floats2half2_rn(r0, r1);
    __half2 h1 = __floats2half2_rn(r2, r3);
    *(uint2*)(outh + (size_t)row * HS + idx) = make_uint2(*(uint32_t*)&h0, *(uint32_t*)&h1);
}

// ---------------- addln #2 (final): out = LN(p0 + p1 + bias + x1h) ---------
__global__ void __launch_bounds__(192)
addln_final(const __half* __restrict__ p0, const __half* __restrict__ p1,
            const float* __restrict__ bias, const __half* __restrict__ resh,
            const float* __restrict__ g, const float* __restrict__ bb,
            float* __restrict__ outf)
{
    __shared__ float wsum[6], wsq[6];
    __shared__ float s_mu, s_rstd;

    const int row = blockIdx.x;
    const int tid = threadIdx.x;
    const int idx = tid * 4;

    uint2 u0 = *(const uint2*)(p0 + (size_t)row * HS + idx);
    uint2 u1 = *(const uint2*)(p1 + (size_t)row * HS + idx);
    uint2 ur = *(const uint2*)(resh + (size_t)row * HS + idx);
    float4 vbias = *(const float4*)(bias + idx);

    float2 p0a = __half22float2(*(__half2*)&u0.x);
    float2 p0b = __half22float2(*(__half2*)&u0.y);
    float2 p1a = __half22float2(*(__half2*)&u1.x);
    float2 p1b = __half22float2(*(__half2*)&u1.y);
    float2 ra  = __half22float2(*(__half2*)&ur.x);
    float2 rb  = __half22float2(*(__half2*)&ur.y);

    float v0 = p0a.x + p1a.x + vbias.x + ra.x;
    float v1 = p0a.y + p1a.y + vbias.y + ra.y;
    float v2 = p0b.x + p1b.x + vbias.z + rb.x;
    float v3 = p0b.y + p1b.y + vbias.w + rb.y;

    float sum = v0 + v1 + v2 + v3;
    float sq  = v0 * v0 + v1 * v1 + v2 * v2 + v3 * v3;
#pragma unroll
    for (int off = 16; off > 0; off >>= 1) {
        sum += __shfl_down_sync(0xffffffffu, sum, off);
        sq  += __shfl_down_sync(0xffffffffu, sq,  off);
    }
    if ((tid & 31) == 0) { wsum[tid >> 5] = sum; wsq[tid >> 5] = sq; }
    __syncthreads();
    if (tid == 0) {
        float s = 0.f, q = 0.f;
#pragma unroll
        for (int i = 0; i < 6; i++) { s += wsum[i]; q += wsq[i]; }
        float mu  = s * (1.f / HS);
        float var = q * (1.f / HS) - mu * mu;
        s_mu = mu;
        s_rstd = rsqrtf(fmaxf(var, 0.f) + 1e-12f);
    }
    __syncthreads();
    const float mu = s_mu, rstd = s_rstd;

    float4 vg = *(const float4*)(g  + idx);
    float4 vb = *(const float4*)(bb + idx);
    float r0 = (v0 - mu) * rstd * vg.x + vb.x;
    float r1 = (v1 - mu) * rstd * vg.y + vb.y;
    float r2 = (v2 - mu) * rstd * vg.z + vb.z;
    float r3 = (v3 - mu) * rstd * vg.w + vb.w;

    *(float4*)(outf + (size_t)row * HS + idx) = make_float4(r0, r1, r2, r3);
}

// ---------------- launch ---------------------------------------------------
extern "C" void kernel_launch(void* const* d_in, const int* in_sizes, int n_in,
                              void* d_out, int out_size)
{
    const float* x     = (const float*)d_in[0];
    const float* w_qkv = (const float*)d_in[1];
    const float* b_qkv = (const float*)d_in[2];
    const float* w_out = (const float*)d_in[3];
    const float* b_out = (const float*)d_in[4];
    const float* w_ff1 = (const float*)d_in[5];
    const float* b_ff1 = (const float*)d_in[6];
    const float* w_ff2 = (const float*)d_in[7];
    const float* b_ff2 = (const float*)d_in[8];
    const float* g1    = (const float*)d_in[9];
    const float* be1   = (const float*)d_in[10];
    const float* g2    = (const float*)d_in[11];
    const float* be2   = (const float*)d_in[12];
    float* out = (float*)d_out;

    __half *xh, *wqkvT, *woutT, *wff1T, *wff2T, *qkvh, *ctxh, *aoh, *x1h, *h1h, *f2p;
    cudaGetSymbolAddress((void**)&xh,    g_xh);
    cudaGetSymbolAddress((void**)&wqkvT, g_wqkvT);
    cudaGetSymbolAddress((void**)&woutT, g_woutT);
    cudaGetSymbolAddress((void**)&wff1T, g_wff1T);
    cudaGetSymbolAddress((void**)&wff2T, g_wff2T);
    cudaGetSymbolAddress((void**)&qkvh,  g_qkvh);
    cudaGetSymbolAddress((void**)&ctxh,  g_ctxh);
    cudaGetSymbolAddress((void**)&aoh,   g_aoh);
    cudaGetSymbolAddress((void**)&x1h,   g_x1h);
    cudaGetSymbolAddress((void**)&h1h,   g_h1h);
    cudaGetSymbolAddress((void**)&f2p,   g_f2p);

    cudaFuncSetAttribute(attn_mma,
                         cudaFuncAttributeMaxDynamicSharedMemorySize, ATTN_SMEM_BYTES);
    cudaFuncSetAttribute(gemm_h<0,0>, cudaFuncAttributeMaxDynamicSharedMemorySize, GH_SMEM_BYTES);
    cudaFuncSetAttribute(gemm_h<1,0>, cudaFuncAttributeMaxDynamicSharedMemorySize, GH_SMEM_BYTES);
    cudaFuncSetAttribute(gemm_h<0,1>, cudaFuncAttributeMaxDynamicSharedMemorySize, GH_SMEM_BYTES);

    // 0) fused pre-pass
    prep_kernel<<<PREP_TOTAL, 256>>>(x, w_qkv, w_out, w_ff1, w_ff2,
                                     xh, wqkvT, woutT, wff1T, wff2T);

    // 1) QKV projection -> fp16 qkv
    gemm_h<0,0><<<dim3(H3 / 128, MM / 128), 256, GH_SMEM_BYTES>>>(
        xh, wqkvT, b_qkv, qkvh, H3, HS);

    // 2) fp16 flash attention -> fp16 ctx
    attn_mma<<<dim3(SS / 128, NH, BB), 256, ATTN_SMEM_BYTES>>>(qkvh, ctxh);

    // 3) output projection -> fp16 ao
    gemm_h<0,0><<<dim3(HS / 128, MM / 128), 256, GH_SMEM_BYTES>>>(
        ctxh, woutT, b_out, aoh, HS, HS);

    // 4) x1h = LN(x + ao)
    addln_mid<<<MM, 192>>>(aoh, x, g1, be1, x1h);

    // 5) h1 = gelu(x1 @ w_ff1 + b_ff1) -> fp16
    gemm_h<1,0><<<dim3(FF / 128, MM / 128), 256, GH_SMEM_BYTES>>>(
        x1h, wff1T, b_ff1, h1h, FF, HS);

    // 6) f2 partials = h1 @ w_ff2 (split-K=2, no bias) -> fp16 x2
    gemm_h<0,1><<<dim3(HS / 128, MM / 128, 2), 256, GH_SMEM_BYTES>>>(
        h1h, wff2T, nullptr, f2p, HS, FF);

    // 7) out = LN(p0 + p1 + b_ff2 + x1h)
    addln_final<<<MM, 192>>>(f2p, f2p + (size_t)MM * HS, b_ff2, x1h,
                             g2, be2, out);
}

// round 17
// speedup vs baseline: 1.0172x; 1.0172x over previous
#include <cuda_runtime.h>
#include <cuda_fp16.h>
#include <math.h>
#include <stdint.h>

#define HS   768
#define NH   12
#define HD   64
#define FF   3072
#define BB   4
#define SS   2048
#define MM   (BB*SS)     /* 8192 rows */
#define H3   (3*HS)      /* 2304 */

// ---------------- scratch (device globals, no allocation) ----------------
__device__ __half g_xh   [(size_t)MM * HS];
__device__ __half g_wqkvT[(size_t)H3 * HS];
__device__ __half g_woutT[(size_t)HS * HS];
__device__ __half g_wff1T[(size_t)FF * HS];
__device__ __half g_wff2T[(size_t)HS * FF];
__device__ __half g_qkvh [(size_t)MM * H3];
__device__ __half g_ctxh [(size_t)MM * HS];
__device__ __half g_aoh  [(size_t)MM * HS];
__device__ __half g_x1h  [(size_t)MM * HS];
__device__ __half g_h1h  [(size_t)MM * FF];
__device__ __half g_f2h  [(size_t)MM * HS];

// ================= helpers ==================================================
__device__ __forceinline__ uint32_t smem_u32(const void* p) {
    uint32_t a;
    asm("{ .reg .u64 t; cvta.to.shared.u64 t, %1; cvt.u32.u64 %0, t; }" : "=r"(a) : "l"(p));
    return a;
}
__device__ __forceinline__ void cp16(uint32_t s, const void* g) {
    asm volatile("cp.async.cg.shared.global [%0], [%1], 16;" :: "r"(s), "l"(g) : "memory");
}
__device__ __forceinline__ void cp_commit() {
    asm volatile("cp.async.commit_group;" ::: "memory");
}
template<int N> __device__ __forceinline__ void cp_wait() {
    asm volatile("cp.async.wait_group %0;" :: "n"(N) : "memory");
}
__device__ __forceinline__ void mma_f16(float c[4], const uint32_t a[4], const uint32_t b[2]) {
    asm volatile(
        "mma.sync.aligned.m16n8k16.row.col.f32.f16.f16.f32 "
        "{%0,%1,%2,%3}, {%4,%5,%6,%7}, {%8,%9}, {%0,%1,%2,%3};"
        : "+f"(c[0]), "+f"(c[1]), "+f"(c[2]), "+f"(c[3])
        : "r"(a[0]), "r"(a[1]), "r"(a[2]), "r"(a[3]), "r"(b[0]), "r"(b[1]));
}
__device__ __forceinline__ void ldmx4(uint32_t r[4], uint32_t addr) {
    asm volatile("ldmatrix.sync.aligned.m8n8.x4.shared.b16 {%0,%1,%2,%3}, [%4];"
                 : "=r"(r[0]), "=r"(r[1]), "=r"(r[2]), "=r"(r[3]) : "r"(addr));
}
__device__ __forceinline__ void ldmx2t(uint32_t& b0, uint32_t& b1, uint32_t addr) {
    asm volatile("ldmatrix.sync.aligned.m8n8.x2.trans.shared.b16 {%0,%1}, [%2];"
                 : "=r"(b0), "=r"(b1) : "r"(addr));
}
__device__ __forceinline__ float ex2f(float x) {
    float y;
    asm("ex2.approx.f32 %0, %1;" : "=f"(y) : "f"(x));
    return y;
}
__device__ __forceinline__ float gelu_exact(float v) {
    return 0.5f * v * (1.0f + erff(v * 0.70710678118654752f));
}

// ---------------- fused pre-pass: f2h(x) + 4 weight transposes -------------
__device__ __forceinline__ void transp_tile(const float* __restrict__ W,
                                            __half* __restrict__ WT,
                                            int K, int N, int bx, int by,
                                            int tx, int ty, float* t /*32x33*/)
{
    const int n0 = bx * 32, k0 = by * 32;
#pragma unroll
    for (int i = 0; i < 4; i++)
        t[(ty + i * 8) * 33 + tx] = W[(size_t)(k0 + ty + i * 8) * N + n0 + tx];
    __syncthreads();
#pragma unroll
    for (int i = 0; i < 4; i++)
        WT[(size_t)(n0 + ty + i * 8) * K + k0 + tx] = __float2half_rn(t[tx * 33 + ty + i * 8]);
}

#define PREP_F2H   6144
#define PREP_QKV   (72 * 24)
#define PREP_OUT   (24 * 24)
#define PREP_FF1   (96 * 24)
#define PREP_FF2   (24 * 96)
#define PREP_TOTAL (PREP_F2H + PREP_QKV + PREP_OUT + PREP_FF1 + PREP_FF2)

__global__ void __launch_bounds__(256)
prep_kernel(const float* __restrict__ x,
            const float* __restrict__ wqkv, const float* __restrict__ wout,
            const float* __restrict__ wff1, const float* __restrict__ wff2,
            __half* __restrict__ xh,
            __half* __restrict__ wqkvT, __half* __restrict__ woutT,
            __half* __restrict__ wff1T, __half* __restrict__ wff2T)
{
    __shared__ float t[32 * 33];
    int blk = blockIdx.x;
    const int tid = threadIdx.x;
    if (blk < PREP_F2H) {
        int i = blk * 256 + tid;
        float4 v = *(const float4*)(x + (size_t)i * 4);
        __half2 h0 = __floats2half2_rn(v.x, v.y);
        __half2 h1 = __floats2half2_rn(v.z, v.w);
        *(uint2*)(xh + (size_t)i * 4) = make_uint2(*(uint32_t*)&h0, *(uint32_t*)&h1);
        return;
    }
    blk -= PREP_F2H;
    const int tx = tid & 31, ty = tid >> 5;
    if (blk < PREP_QKV) {
        transp_tile(wqkv, wqkvT, HS, H3, blk % 72, blk / 72, tx, ty, t);
        return;
    }
    blk -= PREP_QKV;
    if (blk < PREP_OUT) {
        transp_tile(wout, woutT, HS, HS, blk % 24, blk / 24, tx, ty, t);
        return;
    }
    blk -= PREP_OUT;
    if (blk < PREP_FF1) {
        transp_tile(wff1, wff1T, HS, FF, blk % 96, blk / 96, tx, ty, t);
        return;
    }
    blk -= PREP_FF1;
    transp_tile(wff2, wff2T, FF, HS, blk % 24, blk / 24, tx, ty, t);
}

// ---------------- fp16 mma GEMM: BK=64, 3-stage cp.async (R9 config) -------
#define PITCH  72
#define AST    (128 * PITCH)
#define STG_H  (2 * AST)
#define STAGES 3
#define GH_SMEM_BYTES (STAGES * STG_H * 2)

template<int GELU>
__global__ void __launch_bounds__(256, 2)
gemm_h(const __half* __restrict__ A, const __half* __restrict__ WT,
       const float* __restrict__ bias, __half* __restrict__ Ch,
       int N, int K)
{
    extern __shared__ __half hsm[];
    const uint32_t sbase = smem_u32(hsm);

    const int tid  = threadIdx.x;
    const int warp = tid >> 5;
    const int lane = tid & 31;
    const int g    = lane >> 2;
    const int t    = lane & 3;
    const int wm   = warp >> 2;
    const int wn   = warp & 3;
    const int row0 = blockIdx.y * 128;
    const int col0 = blockIdx.x * 128;
    const int KT   = K >> 6;

    const __half* Ab = A  + (size_t)row0 * K;
    const __half* Bb = WT + (size_t)col0 * K;

    const int lm_arow = wm * 64 + (lane & 15);
    const int lm_acol = (lane >> 4) * 8;
    const int lm_brow = wn * 32 + (lane & 7) + ((lane >> 4) << 3);
    const int lm_bcol = ((lane >> 3) & 1) * 8;

    float acc[4][4][4];
#pragma unroll
    for (int mi = 0; mi < 4; mi++)
#pragma unroll
        for (int ni = 0; ni < 4; ni++)
#pragma unroll
            for (int q = 0; q < 4; q++) acc[mi][ni][q] = 0.f;

#pragma unroll
    for (int s = 0; s < 2; s++) {
        const uint32_t sa = sbase + s * STG_H * 2;
        const int k0 = s * 64;
#pragma unroll
        for (int j = 0; j < 4; j++) {
            int item = tid + j * 256;
            int r = item >> 3, c = item & 7;
            cp16(sa + (r * PITCH + c * 8) * 2,       Ab + (size_t)r * K + k0 + c * 8);
            cp16(sa + (AST + r * PITCH + c * 8) * 2, Bb + (size_t)r * K + k0 + c * 8);
        }
        cp_commit();
    }

    int stg = 0;
    for (int it = 0; it < KT; it++) {
        if (it + 1 < KT) cp_wait<1>();
        else             cp_wait<0>();
        __syncthreads();

        if (it + 2 < KT) {
            int s = stg + 2; if (s >= STAGES) s -= STAGES;
            const uint32_t sa = sbase + s * STG_H * 2;
            const int k0 = (it + 2) * 64;
#pragma unroll
            for (int j = 0; j < 4; j++) {
                int item = tid + j * 256;
                int r = item >> 3, c = item & 7;
                cp16(sa + (r * PITCH + c * 8) * 2,       Ab + (size_t)r * K + k0 + c * 8);
                cp16(sa + (AST + r * PITCH + c * 8) * 2, Bb + (size_t)r * K + k0 + c * 8);
            }
            cp_commit();
        }

        const uint32_t cAu = sbase + (uint32_t)(stg * STG_H) * 2;
        const uint32_t cBu = cAu + AST * 2;
#pragma unroll
        for (int ks = 0; ks < 4; ks++) {
            const int kb = ks * 16;
            uint32_t af[4][4], bf[4][2];
#pragma unroll
            for (int mi = 0; mi < 4; mi++)
                ldmx4(af[mi], cAu + (((lm_arow + mi * 16) * PITCH) + kb + lm_acol) * 2);
#pragma unroll
            for (int nip = 0; nip < 2; nip++) {
                uint32_t r[4];
                ldmx4(r, cBu + (((lm_brow + nip * 16) * PITCH) + kb + lm_bcol) * 2);
                bf[nip * 2][0]     = r[0];
                bf[nip * 2][1]     = r[1];
                bf[nip * 2 + 1][0] = r[2];
                bf[nip * 2 + 1][1] = r[3];
            }
#pragma unroll
            for (int mi = 0; mi < 4; mi++)
#pragma unroll
                for (int ni = 0; ni < 4; ni++)
                    mma_f16(acc[mi][ni], af[mi], bf[ni]);
        }
        if (++stg == STAGES) stg = 0;
    }

#pragma unroll
    for (int mi = 0; mi < 4; mi++) {
        const int r0 = row0 + wm * 64 + mi * 16 + g;
#pragma unroll
        for (int ni = 0; ni < 4; ni++) {
            const int c = col0 + wn * 32 + ni * 8 + 2 * t;
            const float b0 = __ldg(bias + c);
            const float b1 = __ldg(bias + c + 1);
            float v0 = acc[mi][ni][0] + b0;
            float v1 = acc[mi][ni][1] + b1;
            float v2 = acc[mi][ni][2] + b0;
            float v3 = acc[mi][ni][3] + b1;
            if (GELU) {
                v0 = gelu_exact(v0); v1 = gelu_exact(v1);
                v2 = gelu_exact(v2); v3 = gelu_exact(v3);
            }
            *(__half2*)(Ch + (size_t)r0 * N + c)       = __floats2half2_rn(v0, v1);
            *(__half2*)(Ch + (size_t)(r0 + 8) * N + c) = __floats2half2_rn(v2, v3);
        }
    }
}

// ---------------- fp16 flash attention (2-buffer, 2 CTAs/SM) ---------------
// Q is pre-scaled by 0.125*log2(e) at staging -> scores in log2 domain,
// softmax uses ex2.approx directly (no per-element scale or LOG2E muls).
#define HP 72
#define AQ_OFF 0
#define AK_OFF (128 * HP)
#define AV_OFF (128 * HP + 2 * 64 * HP)
#define ATTN_SMEM_BYTES ((128 * HP + 4 * 64 * HP) * 2)

__global__ void __launch_bounds__(256, 2)
attn_mma(const __half* __restrict__ qkvh, __half* __restrict__ ctxh)
{
    extern __shared__ __half hsm[];
    __half* sQ = hsm + AQ_OFF;
    const uint32_t sb = smem_u32(hsm);

    const int tid  = threadIdx.x;
    const int warp = tid >> 5;
    const int lane = tid & 31;
    const int g    = lane >> 2;
    const int t    = lane & 3;
    const int m0   = warp * 16;
    const int l16  = lane & 15;

    const int q0 = blockIdx.x * 128;
    const int h  = blockIdx.y;
    const int b  = blockIdx.z;

    const __half* Qg = qkvh + ((size_t)(b * SS) + q0) * H3 + h * HD;
    const __half* Kg = qkvh + (size_t)(b * SS) * H3 + HS     + h * HD;
    const __half* Vg = qkvh + (size_t)(b * SS) * H3 + 2 * HS + h * HD;

    const int lm_krow = (lane & 7) + ((lane >> 4) << 3);
    const int lm_kcol = ((lane >> 3) & 1) * 8;

    // stage Q pre-scaled by 0.125 * log2(e)
    const __half2 qsc = __float2half2_rn(0.18033688011112042f);
#pragma unroll
    for (int it = 0; it < 4; it++) {
        int item = tid + it * 256;
        int r = item >> 3, c = item & 7;
        uint4 u = *(const uint4*)(Qg + (size_t)r * H3 + c * 8);
        __half2* hp = (__half2*)&u;
#pragma unroll
        for (int q = 0; q < 4; q++) hp[q] = __hmul2(hp[q], qsc);
        *(uint4*)(sQ + r * HP + c * 8) = u;
    }

    {
        const uint32_t ka = sb + AK_OFF * 2;
        const uint32_t va = sb + AV_OFF * 2;
#pragma unroll
        for (int it = 0; it < 2; it++) {
            int item = tid + it * 256;
            int j = item >> 3, c = item & 7;
            const size_t go = (size_t)j * H3 + c * 8;
            cp16(ka + (j * HP + c * 8) * 2, Kg + go);
            cp16(va + (j * HP + c * 8) * 2, Vg + go);
        }
        cp_commit();
    }
    __syncthreads();

    uint32_t qf[4][4];
#pragma unroll
    for (int kb = 0; kb < 4; kb++) {
        qf[kb][0] = *(const uint32_t*)(sQ + (m0 + g)     * HP + kb * 16 + 2 * t);
        qf[kb][1] = *(const uint32_t*)(sQ + (m0 + g + 8) * HP + kb * 16 + 2 * t);
        qf[kb][2] = *(const uint32_t*)(sQ + (m0 + g)     * HP + kb * 16 + 8 + 2 * t);
        qf[kb][3] = *(const uint32_t*)(sQ + (m0 + g + 8) * HP + kb * 16 + 8 + 2 * t);
    }

    float mrow0 = -1e30f, mrow1 = -1e30f;
    float lrow0 = 0.f,    lrow1 = 0.f;
    float o[8][4];
#pragma unroll
    for (int ni = 0; ni < 8; ni++)
#pragma unroll
        for (int q = 0; q < 4; q++) o[ni][q] = 0.f;

    const int NT = SS / 64;

    for (int kt = 0; kt < NT; kt++) {
        cp_wait<0>();
        __syncthreads();

        const int buf = kt & 1;
        const uint32_t skb = sb + (AK_OFF + buf * 64 * HP) * 2;
        const uint32_t svb = sb + (AV_OFF + buf * 64 * HP) * 2;

        if (kt + 1 < NT) {
            const int nb = buf ^ 1;
            const uint32_t ka = sb + (AK_OFF + nb * 64 * HP) * 2;
            const uint32_t va = sb + (AV_OFF + nb * 64 * HP) * 2;
#pragma unroll
            for (int it = 0; it < 2; it++) {
                int item = tid + it * 256;
                int j = item >> 3, c = item & 7;
                const size_t go = (size_t)((kt + 1) * 64 + j) * H3 + c * 8;
                cp16(ka + (j * HP + c * 8) * 2, Kg + go);
                cp16(va + (j * HP + c * 8) * 2, Vg + go);
            }
            cp_commit();
        }

        float s_[8][4];
#pragma unroll
        for (int ni = 0; ni < 8; ni++)
#pragma unroll
            for (int q = 0; q < 4; q++) s_[ni][q] = 0.f;

#pragma unroll
        for (int kb = 0; kb < 4; kb++) {
#pragma unroll
            for (int nip = 0; nip < 4; nip++) {
                uint32_t r[4];
                ldmx4(r, skb + (((nip * 16 + lm_krow) * HP) + kb * 16 + lm_kcol) * 2);
                uint32_t bf0[2] = { r[0], r[1] };
                uint32_t bf1[2] = { r[2], r[3] };
                mma_f16(s_[nip * 2],     qf[kb], bf0);
                mma_f16(s_[nip * 2 + 1], qf[kb], bf1);
            }
        }

        // log2-domain online softmax
        float mn0 = -1e30f, mn1 = -1e30f;
#pragma unroll
        for (int ni = 0; ni < 8; ni++) {
            mn0 = fmaxf(mn0, fmaxf(s_[ni][0], s_[ni][1]));
            mn1 = fmaxf(mn1, fmaxf(s_[ni][2], s_[ni][3]));
        }
        mn0 = fmaxf(mn0, __shfl_xor_sync(0xffffffffu, mn0, 1));
        mn0 = fmaxf(mn0, __shfl_xor_sync(0xffffffffu, mn0, 2));
        mn1 = fmaxf(mn1, __shfl_xor_sync(0xffffffffu, mn1, 1));
        mn1 = fmaxf(mn1, __shfl_xor_sync(0xffffffffu, mn1, 2));

        const float mnew0 = fmaxf(mrow0, mn0);
        const float mnew1 = fmaxf(mrow1, mn1);
        const float a0 = ex2f(mrow0 - mnew0);
        const float a1 = ex2f(mrow1 - mnew1);
        mrow0 = mnew0; mrow1 = mnew1;

        float ladd0 = 0.f, ladd1 = 0.f;
#pragma unroll
        for (int ni = 0; ni < 8; ni++) {
            s_[ni][0] = ex2f(s_[ni][0] - mnew0);
            s_[ni][1] = ex2f(s_[ni][1] - mnew0);
            s_[ni][2] = ex2f(s_[ni][2] - mnew1);
            s_[ni][3] = ex2f(s_[ni][3] - mnew1);
            ladd0 += s_[ni][0] + s_[ni][1];
            ladd1 += s_[ni][2] + s_[ni][3];
            o[ni][0] *= a0; o[ni][1] *= a0;
            o[ni][2] *= a1; o[ni][3] *= a1;
        }
        ladd0 += __shfl_xor_sync(0xffffffffu, ladd0, 1);
        ladd0 += __shfl_xor_sync(0xffffffffu, ladd0, 2);
        ladd1 += __shfl_xor_sync(0xffffffffu, ladd1, 1);
        ladd1 += __shfl_xor_sync(0xffffffffu, ladd1, 2);
        lrow0 = lrow0 * a0 + ladd0;
        lrow1 = lrow1 * a1 + ladd1;

#pragma unroll
        for (int kb = 0; kb < 4; kb++) {
            uint32_t af[4];
            {
                __half2 h0 = __floats2half2_rn(s_[2 * kb][0],     s_[2 * kb][1]);
                __half2 h1 = __floats2half2_rn(s_[2 * kb][2],     s_[2 * kb][3]);
                __half2 h2 = __floats2half2_rn(s_[2 * kb + 1][0], s_[2 * kb + 1][1]);
                __half2 h3 = __floats2half2_rn(s_[2 * kb + 1][2], s_[2 * kb + 1][3]);
                af[0] = *(uint32_t*)&h0;
                af[1] = *(uint32_t*)&h1;
                af[2] = *(uint32_t*)&h2;
                af[3] = *(uint32_t*)&h3;
            }
            const uint32_t rowaddr = svb + ((kb * 16 + l16) * HP) * 2;
#pragma unroll
            for (int ni = 0; ni < 8; ni++) {
                uint32_t bf0, bf1;
                ldmx2t(bf0, bf1, rowaddr + ni * 16);
                uint32_t bf[2] = { bf0, bf1 };
                mma_f16(o[ni], af, bf);
            }
        }
    }

    const float inv0 = 1.0f / lrow0;
    const float inv1 = 1.0f / lrow1;
    const int qr0 = q0 + m0 + g;
    __half* dst0 = ctxh + ((size_t)(b * SS) + qr0)     * HS + h * HD;
    __half* dst1 = ctxh + ((size_t)(b * SS) + qr0 + 8) * HS + h * HD;
#pragma unroll
    for (int ni = 0; ni < 8; ni++) {
        const int c = ni * 8 + 2 * t;
        *(__half2*)(dst0 + c) = __floats2half2_rn(o[ni][0] * inv0, o[ni][1] * inv0);
        *(__half2*)(dst1 + c) = __floats2half2_rn(o[ni][2] * inv1, o[ni][3] * inv1);
    }
}

// ---------------- residual add + LayerNorm, vectorized ---------------------
template<int RESF, int OUTF, int WH>
__global__ void __launch_bounds__(192)
addln_kernel(const __half* __restrict__ a,
             const float* __restrict__ resf, const __half* __restrict__ resh,
             const float* __restrict__ g, const float* __restrict__ bb,
             float* __restrict__ outf, __half* __restrict__ outh)
{
    __shared__ float wsum[6], wsq[6];
    __shared__ float s_mu, s_rstd;

    const int row = blockIdx.x;
    const int tid = threadIdx.x;
    const int idx = tid * 4;

    uint2 ua = *(const uint2*)(a + (size_t)row * HS + idx);
    float2 a01 = __half22float2(*(__half2*)&ua.x);
    float2 a23 = __half22float2(*(__half2*)&ua.y);

    float r0v, r1v, r2v, r3v;
    if (RESF) {
        float4 vr = *(const float4*)(resf + (size_t)row * HS + idx);
        r0v = vr.x; r1v = vr.y; r2v = vr.z; r3v = vr.w;
    } else {
        uint2 ur = *(const uint2*)(resh + (size_t)row * HS + idx);
        float2 r01 = __half22float2(*(__half2*)&ur.x);
        float2 r23 = __half22float2(*(__half2*)&ur.y);
        r0v = r01.x; r1v = r01.y; r2v = r23.x; r3v = r23.y;
    }

    float v0 = a01.x + r0v;
    float v1 = a01.y + r1v;
    float v2 = a23.x + r2v;
    float v3 = a23.y + r3v;

    float sum = v0 + v1 + v2 + v3;
    float sq  = v0 * v0 + v1 * v1 + v2 * v2 + v3 * v3;
#pragma unroll
    for (int off = 16; off > 0; off >>= 1) {
        sum += __shfl_down_sync(0xffffffffu, sum, off);
        sq  += __shfl_down_sync(0xffffffffu, sq,  off);
    }
    if ((tid & 31) == 0) { wsum[tid >> 5] = sum; wsq[tid >> 5] = sq; }
    __syncthreads();
    if (tid == 0) {
        float s = 0.f, q = 0.f;
#pragma unroll
        for (int i = 0; i < 6; i++) { s += wsum[i]; q += wsq[i]; }
        float mu  = s * (1.f / HS);
        float var = q * (1.f / HS) - mu * mu;
        s_mu = mu;
        s_rstd = rsqrtf(fmaxf(var, 0.f) + 1e-12f);
    }
    __syncthreads();
    const float mu = s_mu, rstd = s_rstd;

    float4 vg = *(const float4*)(g  + idx);
    float4 vb = *(const float4*)(bb + idx);
    float r0 = (v0 - mu) * rstd * vg.x + vb.x;
    float r1 = (v1 - mu) * rstd * vg.y + vb.y;
    float r2 = (v2 - mu) * rstd * vg.z + vb.z;
    float r3 = (v3 - mu) * rstd * vg.w + vb.w;

    if (OUTF)
        *(float4*)(outf + (size_t)row * HS + idx) = make_float4(r0, r1, r2, r3);
    if (WH) {
        __half2 h0 = __floats2half2_rn(r0, r1);
        __half2 h1 = __floats2half2_rn(r2, r3);
        *(uint2*)(outh + (size_t)row * HS + idx) = make_uint2(*(uint32_t*)&h0, *(uint32_t*)&h1);
    }
}

// ---------------- launch ---------------------------------------------------
extern "C" void kernel_launch(void* const* d_in, const int* in_sizes, int n_in,
                              void* d_out, int out_size)
{
    const float* x     = (const float*)d_in[0];
    const float* w_qkv = (const float*)d_in[1];
    const float* b_qkv = (const float*)d_in[2];
    const float* w_out = (const float*)d_in[3];
    const float* b_out = (const float*)d_in[4];
    const float* w_ff1 = (const float*)d_in[5];
    const float* b_ff1 = (const float*)d_in[6];
    const float* w_ff2 = (const float*)d_in[7];
    const float* b_ff2 = (const float*)d_in[8];
    const float* g1    = (const float*)d_in[9];
    const float* be1   = (const float*)d_in[10];
    const float* g2    = (const float*)d_in[11];
    const float* be2   = (const float*)d_in[12];
    float* out = (float*)d_out;

    __half *xh, *wqkvT, *woutT, *wff1T, *wff2T, *qkvh, *ctxh, *aoh, *x1h, *h1h, *f2h;
    cudaGetSymbolAddress((void**)&xh,    g_xh);
    cudaGetSymbolAddress((void**)&wqkvT, g_wqkvT);
    cudaGetSymbolAddress((void**)&woutT, g_woutT);
    cudaGetSymbolAddress((void**)&wff1T, g_wff1T);
    cudaGetSymbolAddress((void**)&wff2T, g_wff2T);
    cudaGetSymbolAddress((void**)&qkvh,  g_qkvh);
    cudaGetSymbolAddress((void**)&ctxh,  g_ctxh);
    cudaGetSymbolAddress((void**)&aoh,   g_aoh);
    cudaGetSymbolAddress((void**)&x1h,   g_x1h);
    cudaGetSymbolAddress((void**)&h1h,   g_h1h);
    cudaGetSymbolAddress((void**)&f2h,   g_f2h);

    cudaFuncSetAttribute(attn_mma,
                         cudaFuncAttributeMaxDynamicSharedMemorySize, ATTN_SMEM_BYTES);
    cudaFuncSetAttribute(gemm_h<0>, cudaFuncAttributeMaxDynamicSharedMemorySize, GH_SMEM_BYTES);
    cudaFuncSetAttribute(gemm_h<1>, cudaFuncAttributeMaxDynamicSharedMemorySize, GH_SMEM_BYTES);

    // 0) fused pre-pass
    prep_kernel<<<PREP_TOTAL, 256>>>(x, w_qkv, w_out, w_ff1, w_ff2,
                                     xh, wqkvT, woutT, wff1T, wff2T);

    // 1) QKV projection -> fp16 qkv
    gemm_h<0><<<dim3(H3 / 128, MM / 128), 256, GH_SMEM_BYTES>>>(
        xh, wqkvT, b_qkv, qkvh, H3, HS);

    // 2) fp16 flash attention -> fp16 ctx
    attn_mma<<<dim3(SS / 128, NH, BB), 256, ATTN_SMEM_BYTES>>>(qkvh, ctxh);

    // 3) output projection -> fp16 ao
    gemm_h<0><<<dim3(HS / 128, MM / 128), 256, GH_SMEM_BYTES>>>(
        ctxh, woutT, b_out, aoh, HS, HS);

    // 4) x1h = LN(x + ao)
    addln_kernel<1, 0, 1><<<MM, 192>>>(aoh, x, nullptr, g1, be1, nullptr, x1h);

    // 5) h1 = gelu(x1 @ w_ff1 + b_ff1) -> fp16
    gemm_h<1><<<dim3(FF / 128, MM / 128), 256, GH_SMEM_BYTES>>>(
        x1h, wff1T, b_ff1, h1h, FF, HS);

    // 6) f2 = h1 @ w_ff2 + b_ff2 -> fp16
    gemm_h<0><<<dim3(HS / 128, MM / 128), 256, GH_SMEM_BYTES>>>(
        h1h, wff2T, b_ff2, f2h, HS, FF);

    // 7) out = LN(x1h + f2)
    addln_kernel<0, 1, 0><<<MM, 192>>>(f2h, nullptr, x1h, g2, be2, out, nullptr);
}